// round 14
// baseline (speedup 1.0000x reference)
#include <cuda_runtime.h>
#include <cuda_fp16.h>
#include <math.h>
#include <stdint.h>

#define TOK  4096
#define CH   768
#define NSEQ 1024
#define BHD  48
#define HD   64
#define MLPD 3072
#define QKVD 2304

// ---------------- scratch (device globals; no allocations) ----------------
__device__ float  g_h   [TOK*CH];
__device__ __half g_lnh [TOK*CH];
__device__ __half g_colh[TOK*CH];
__device__ __half g_wth [CH*CH];
__device__ __half g_qh  [BHD*NSEQ*HD];   // [bh][key][d], pre-scaled by 0.125
__device__ __half g_kh  [BHD*NSEQ*HD];   // [bh][key][d]
__device__ __half g_vh  [BHD*HD*NSEQ];   // [bh][d][key]  (transposed!)
__device__ float  g_relh[BHD*NSEQ*32];
__device__ float  g_relw[BHD*NSEQ*32];
__device__ __half g_aoh [TOK*CH];
__device__ __half g_mlph[TOK*MLPD];
// transposed [n][k] half weights
__device__ __half g_wqkvh[4*CH*QKVD];
__device__ __half g_wprojh[4*CH*CH];
__device__ __half g_wfc1h[4*CH*MLPD];
__device__ __half g_wfc2h[4*MLPD*CH];

// ---------------- helpers ----------------
__device__ __forceinline__ void mma_f16(float* c, const uint32_t* a, const uint32_t* b) {
    asm volatile(
        "mma.sync.aligned.m16n8k16.row.col.f32.f16.f16.f32 "
        "{%0,%1,%2,%3}, {%4,%5,%6,%7}, {%8,%9}, {%0,%1,%2,%3};\n"
        : "+f"(c[0]), "+f"(c[1]), "+f"(c[2]), "+f"(c[3])
        : "r"(a[0]), "r"(a[1]), "r"(a[2]), "r"(a[3]), "r"(b[0]), "r"(b[1]));
}

__device__ __forceinline__ void ldsm4(uint32_t* r, uint32_t addr) {
    asm volatile("ldmatrix.sync.aligned.m8n8.x4.shared.b16 {%0,%1,%2,%3}, [%4];"
        : "=r"(r[0]), "=r"(r[1]), "=r"(r[2]), "=r"(r[3]) : "r"(addr));
}

__device__ __forceinline__ void cp16(uint32_t saddr, const void* g) {
    asm volatile("cp.async.ca.shared.global [%0], [%1], 16;" :: "r"(saddr), "l"(g));
}

// ---------------- prep kernels ----------------
__global__ void wtrans_k(const float* __restrict__ w, __half* __restrict__ wt,
                         int K, int N) {
    __shared__ float t[32][33];
    size_t lo = (size_t)blockIdx.z * K * N;
    const float* wl = w + lo;
    __half* wtl = wt + lo;
    int k0 = blockIdx.x * 32, n0 = blockIdx.y * 32;
    int tx = threadIdx.x, ty = threadIdx.y;
#pragma unroll
    for (int r = 0; r < 32; r += 8)
        t[ty + r][tx] = wl[(size_t)(k0 + ty + r) * N + n0 + tx];
    __syncthreads();
#pragma unroll
    for (int r = 0; r < 32; r += 8)
        wtl[(size_t)(n0 + ty + r) * K + k0 + tx] = __float2half(t[tx][ty + r]);
}

__global__ void convhalf_k(const float* __restrict__ x, __half* __restrict__ y) {
    int idx = blockIdx.x * 256 + threadIdx.x;
    y[idx] = __float2half(x[idx]);
}

__global__ void im2col_k(const float* __restrict__ x, __half* __restrict__ out) {
    int idx = blockIdx.x * 256 + threadIdx.x;
    int token = idx / 768, kk = idx % 768;
    int ci = kk >> 8, r = kk & 255, py = r >> 4, px = r & 15;
    int b = token >> 10, g = token & 1023, gy = g >> 5, gx = g & 31;
    out[idx] = __float2half(
        x[(((size_t)(b*3 + ci) * 512) + gy*16 + py) * 512 + gx*16 + px]);
}

// rel bias from half q (pre-scaled by 0.125 -> compensate with *8)
__global__ void rel_k(const __half* __restrict__ q,
                      const float* __restrict__ rph, const float* __restrict__ rpw,
                      float* __restrict__ relh, float* __restrict__ relw) {
    int gw   = blockIdx.x * 8 + (threadIdx.x >> 5);
    int lane = threadIdx.x & 31;
    int bh = gw >> 10, qi = gw & 1023;
    int qy = qi >> 5, qx = qi & 31;
    const __half2* qp = (const __half2*)(q + ((size_t)bh * NSEQ + qi) * HD);
    const float* rh = rph + (qy - lane + 31) * HD;
    const float* rw = rpw + (qx - lane + 31) * HD;
    float sh = 0.f, sw = 0.f;
#pragma unroll
    for (int d = 0; d < 32; d++) {
        float2 qf = __half22float2(qp[d]);
        sh += qf.x * rh[2*d] + qf.y * rh[2*d+1];
        sw += qf.x * rw[2*d] + qf.y * rw[2*d+1];
    }
    relh[(size_t)gw * 32 + lane] = sh * 8.f;
    relw[(size_t)gw * 32 + lane] = sw * 8.f;
}

__global__ void layernorm_k(const float* __restrict__ x, const float* __restrict__ w,
                            const float* __restrict__ b, __half* __restrict__ y) {
    int row = blockIdx.x;
    const float* xr = x + (size_t)row * CH;
    int t = threadIdx.x;
    float v0 = xr[t], v1 = xr[t+256], v2 = xr[t+512];
    __shared__ float red[256];
    red[t] = v0 + v1 + v2;
    __syncthreads();
    for (int o = 128; o > 0; o >>= 1) { if (t < o) red[t] += red[t+o]; __syncthreads(); }
    float mean = red[0] * (1.f/768.f);
    __syncthreads();
    float d0 = v0-mean, d1 = v1-mean, d2 = v2-mean;
    red[t] = d0*d0 + d1*d1 + d2*d2;
    __syncthreads();
    for (int o = 128; o > 0; o >>= 1) { if (t < o) red[t] += red[t+o]; __syncthreads(); }
    float rstd = rsqrtf(red[0] * (1.f/768.f) + 1e-5f);
    __half* yr = y + (size_t)row * CH;
    yr[t]     = __float2half(d0 * rstd * w[t]     + b[t]);
    yr[t+256] = __float2half(d1 * rstd * w[t+256] + b[t+256]);
    yr[t+512] = __float2half(d2 * rstd * w[t+512] + b[t+512]);
}

// ---------------- fp16 cp.async double-buffered GEMM (ldmatrix fragments) ------------
// EPI: 1 = bias+GELU -> half Ch, 2 = bias+residual -> fp32 C,
//      3 = qkv scatter -> half qh(Ch, scaled), kh, vh(transposed),
//      4 = bias + pos-embed add -> fp32 C
template <int EPI>
__global__ void __launch_bounds__(256)
gemm_h(const __half* __restrict__ A, const __half* __restrict__ Bt,
       const float* __restrict__ bias, const float* __restrict__ res,
       float* __restrict__ C, __half* __restrict__ Ch,
       __half* __restrict__ kh, __half* __restrict__ vh,
       int M, int N, int K) {
    __shared__ __half As[2][128][40];
    __shared__ __half Bs[2][128][40];

    int tx = threadIdx.x;
    int wid = tx >> 5, lane = tx & 31;
    int warpM = wid & 3, warpN = wid >> 2;
    int g = lane >> 2, tg = lane & 3;
    int brow = blockIdx.y * 128, bcol = blockIdx.x * 128;

    uint32_t sA = (uint32_t)__cvta_generic_to_shared(&As[0][0][0]);
    uint32_t sB = (uint32_t)__cvta_generic_to_shared(&Bs[0][0][0]);

    // ldmatrix lane address components
    int laneA_row = lane & 15;
    int laneA_col = (lane >> 4) << 3;
    int laneB_row = ((lane >> 4) << 3) + (lane & 7);
    int laneB_col = ((lane >> 3) & 1) << 3;

    float acc[2][8][4];
#pragma unroll
    for (int i = 0; i < 2; i++)
#pragma unroll
        for (int j = 0; j < 8; j++)
#pragma unroll
            for (int l = 0; l < 4; l++) acc[i][j][l] = 0.f;

    int KT = K >> 5;

#define LOAD_STAGE(st, k0)                                                        \
    {                                                                             \
        _Pragma("unroll")                                                         \
        for (int i = 0; i < 2; i++) {                                             \
            int t4 = tx + i * 256;                                                \
            int m = t4 >> 2, c8 = t4 & 3;                                         \
            cp16(sA + ((st)*128*40 + m*40 + c8*8)*2,                              \
                 &A[(size_t)(brow + m) * K + (k0) + c8*8]);                       \
            cp16(sB + ((st)*128*40 + m*40 + c8*8)*2,                              \
                 &Bt[(size_t)(bcol + m) * K + (k0) + c8*8]);                      \
        }                                                                         \
    }

    LOAD_STAGE(0, 0);
    asm volatile("cp.async.commit_group;");

    for (int kt = 0; kt < KT; kt++) {
        if (kt + 1 < KT) {
            LOAD_STAGE((kt+1)&1, (kt+1)*32);
            asm volatile("cp.async.commit_group;");
            asm volatile("cp.async.wait_group 1;");
        } else {
            asm volatile("cp.async.wait_group 0;");
        }
        __syncthreads();

        uint32_t stoff = (uint32_t)((kt&1)*128*40*2);
        uint32_t aBase = sA + stoff + ((warpM*32 + laneA_row)*40 + laneA_col)*2;
        uint32_t bBase = sB + stoff + ((warpN*64 + laneB_row)*40 + laneB_col)*2;
#pragma unroll
        for (int kk = 0; kk < 32; kk += 16) {
            uint32_t a[2][4], b[8][2];
#pragma unroll
            for (int mt = 0; mt < 2; mt++)
                ldsm4(a[mt], aBase + (mt*16*40 + kk)*2);
#pragma unroll
            for (int np = 0; np < 4; np++) {
                uint32_t t4r[4];
                ldsm4(t4r, bBase + (np*16*40 + kk)*2);
                b[2*np  ][0] = t4r[0]; b[2*np  ][1] = t4r[1];
                b[2*np+1][0] = t4r[2]; b[2*np+1][1] = t4r[3];
            }
#pragma unroll
            for (int mt = 0; mt < 2; mt++)
#pragma unroll
                for (int nt = 0; nt < 8; nt++)
                    mma_f16(acc[mt][nt], a[mt], b[nt]);
        }
        __syncthreads();
    }
#undef LOAD_STAGE

#pragma unroll
    for (int mt = 0; mt < 2; mt++) {
#pragma unroll
        for (int nt = 0; nt < 8; nt++) {
            int r0 = brow + warpM*32 + mt*16 + g;
            int c0 = bcol + warpN*64 + nt*8 + tg*2;
#pragma unroll
            for (int e = 0; e < 4; e++) {
                int row = r0 + (e >> 1) * 8;
                int col = c0 + (e & 1);
                float v = acc[mt][nt][e] + bias[col];
                if (EPI == 1) {
                    v = 0.5f * v * (1.f + erff(v * 0.70710678118f));
                    Ch[(size_t)row * N + col] = __float2half(v);
                } else if (EPI == 2) {
                    C[(size_t)row * N + col] = v + res[(size_t)row * N + col];
                } else if (EPI == 3) {
                    int which = col / 768, rem = col - which * 768;
                    int head = rem >> 6, d = rem & 63;
                    int b_ = row >> 10, n_ = row & 1023;
                    if (which == 0)
                        Ch[((size_t)(b_*12 + head) * NSEQ + n_) * HD + d] =
                            __float2half(v * 0.125f);
                    else if (which == 1)
                        kh[((size_t)(b_*12 + head) * NSEQ + n_) * HD + d] =
                            __float2half(v);
                    else
                        vh[((size_t)(b_*12 + head) * HD + d) * NSEQ + n_] =
                            __float2half(v);
                } else if (EPI == 4) {
                    C[(size_t)row * N + col] = v + res[(size_t)(row & 1023) * CH + col];
                } else {
                    C[(size_t)row * N + col] = v;
                }
            }
        }
    }
}

// ---------------- fp16 fused flash attention (ldmatrix fragments) --------------------
// float region: RH 0, RW 4224, Ms 8448, Ls 8576, Al 8704, Pmax 8832, Psum 9088 (end 9344)
// half  region: Qs 0 [128][72], Ks 9216 [128][72], Vs 18432 [64][136], Ps 27136 [128][136]
#define FA_FLOATS 9344
#define FA_HALVES 44544
#define FA_SMEM_BYTES (FA_FLOATS*4 + FA_HALVES*2)

__global__ void __launch_bounds__(256)
flash_attn(const __half* __restrict__ qh, const __half* __restrict__ kh,
           const __half* __restrict__ vh,
           const float* __restrict__ relh, const float* __restrict__ relw,
           __half* __restrict__ out) {
    extern __shared__ float sm[];
    float* RH = sm;
    float* RW = sm + 4224;
    float* Ms = sm + 8448;
    float* Ls = sm + 8576;
    float* Al = sm + 8704;
    float* Pmax = sm + 8832;
    float* Psum = sm + 9088;
    __half* hb = (__half*)(sm + FA_FLOATS);
    __half* Qs = hb;
    __half* Ks = hb + 9216;
    __half* Vs = hb + 18432;
    __half* Ps = hb + 27136;

    int tx = threadIdx.x;
    int wid = tx >> 5, lane = tx & 31;
    int g = lane >> 2, tg = lane & 3;
    int qt = blockIdx.x, bh = blockIdx.y;
    int warpM  = wid & 3, warpN  = wid >> 2;   // S phase: 32x64 warp tiles
    int warpM2 = wid >> 1, warpN2 = wid & 1;   // O phase: 32x32 warp tiles

    int laneA_row = lane & 15;
    int laneA_col = (lane >> 4) << 3;
    int laneB_row = ((lane >> 4) << 3) + (lane & 7);
    int laneB_col = ((lane >> 3) & 1) << 3;

    const __half* Qg = qh + ((size_t)bh * NSEQ + qt * 128) * HD;
    const __half* Kg = kh + (size_t)bh * NSEQ * HD;
    const __half* Vg = vh + (size_t)bh * HD * NSEQ;

    uint32_t sQ = (uint32_t)__cvta_generic_to_shared(Qs);
    uint32_t sK = (uint32_t)__cvta_generic_to_shared(Ks);
    uint32_t sV = (uint32_t)__cvta_generic_to_shared(Vs);
    uint32_t sP = (uint32_t)__cvta_generic_to_shared(Ps);

    // stage Q via cp.async: 128 rows x 64 halves = 8 chunks/row -> 1024 chunks
#pragma unroll
    for (int i = 0; i < 4; i++) {
        int t4 = tx + i * 256;
        int row = t4 >> 3, c8 = t4 & 7;
        cp16(sQ + (row*72 + c8*8)*2, &Qg[row * HD + c8*8]);
    }
    asm volatile("cp.async.commit_group;");
    // stage rel tables (stride 33)
    for (int idx = tx; idx < 4096; idx += 256) {
        int row = idx >> 5, c = idx & 31;
        size_t src = ((size_t)bh * NSEQ + qt * 128 + row) * 32 + c;
        RH[row*33 + c] = relh[src];
        RW[row*33 + c] = relw[src];
    }
    if (tx < 128) { Ms[tx] = -1e30f; Ls[tx] = 0.f; }

    float o[2][4][4];
#pragma unroll
    for (int a = 0; a < 2; a++)
#pragma unroll
        for (int b = 0; b < 4; b++)
#pragma unroll
            for (int c = 0; c < 4; c++) o[a][b][c] = 0.f;

    // ldmatrix base addresses (stage-invariant)
    uint32_t qBase = sQ + ((warpM*32 + laneA_row)*72 + laneA_col)*2;
    uint32_t kBase = sK + ((warpN*64 + laneB_row)*72 + laneB_col)*2;
    uint32_t pBase = sP + ((warpM2*32 + laneA_row)*136 + laneA_col)*2;
    uint32_t vBase = sV + ((warpN2*32 + laneB_row)*136 + laneB_col)*2;

    for (int kt = 0; kt < 8; kt++) {
        __syncthreads();   // protect Ks/Vs/Ps reuse from previous iteration
        // K tile: 128 keys x 64 dims = 8 chunks/row -> 1024 chunks
#pragma unroll
        for (int i = 0; i < 4; i++) {
            int t4 = tx + i * 256;
            int row = t4 >> 3, c8 = t4 & 7;
            cp16(sK + (row*72 + c8*8)*2, &Kg[(kt*128 + row) * HD + c8*8]);
        }
        // V tile: 64 dims x 128 keys = 16 chunks/row -> 1024 chunks
#pragma unroll
        for (int i = 0; i < 4; i++) {
            int t4 = tx + i * 256;
            int d = t4 >> 4, c8 = t4 & 15;
            cp16(sV + (d*136 + c8*8)*2, &Vg[(size_t)d * NSEQ + kt*128 + c8*8]);
        }
        asm volatile("cp.async.commit_group;");
        asm volatile("cp.async.wait_group 0;");
        __syncthreads();

        // S = Qs @ Ks^T  (K = 64, 4 k16 steps)
        float s[2][8][4];
#pragma unroll
        for (int a = 0; a < 2; a++)
#pragma unroll
            for (int b = 0; b < 8; b++)
#pragma unroll
                for (int c = 0; c < 4; c++) s[a][b][c] = 0.f;
#pragma unroll
        for (int ks = 0; ks < 4; ks++) {
            int kk = ks * 16;
            uint32_t a[2][4], b[8][2];
#pragma unroll
            for (int mt = 0; mt < 2; mt++)
                ldsm4(a[mt], qBase + (mt*16*72 + kk)*2);
#pragma unroll
            for (int np = 0; np < 4; np++) {
                uint32_t t4r[4];
                ldsm4(t4r, kBase + (np*16*72 + kk)*2);
                b[2*np  ][0] = t4r[0]; b[2*np  ][1] = t4r[1];
                b[2*np+1][0] = t4r[2]; b[2*np+1][1] = t4r[3];
            }
#pragma unroll
            for (int mt = 0; mt < 2; mt++)
#pragma unroll
                for (int nt = 0; nt < 8; nt++)
                    mma_f16(s[mt][nt], a[mt], b[nt]);
        }

        // + rel bias; row-wise running max
        float rmax[2][2];
#pragma unroll
        for (int mt = 0; mt < 2; mt++)
#pragma unroll
            for (int rr = 0; rr < 2; rr++) {
                int row = warpM*32 + mt*16 + rr*8 + g;
                float rh0 = RH[row*33 + kt*4 + warpN*2];
                float rh1 = RH[row*33 + kt*4 + warpN*2 + 1];
                float mx = -1e30f;
#pragma unroll
                for (int nt = 0; nt < 8; nt++) {
#pragma unroll
                    for (int e1 = 0; e1 < 2; e1++) {
                        float rw = RW[row*33 + 8*(nt & 3) + 2*tg + e1];
                        float vv = s[mt][nt][rr*2 + e1] + ((nt < 4) ? rh0 : rh1) + rw;
                        s[mt][nt][rr*2 + e1] = vv;
                        mx = fmaxf(mx, vv);
                    }
                }
                rmax[mt][rr] = mx;
            }
#pragma unroll
        for (int mt = 0; mt < 2; mt++)
#pragma unroll
            for (int rr = 0; rr < 2; rr++) {
                float v = rmax[mt][rr];
                v = fmaxf(v, __shfl_xor_sync(0xffffffffu, v, 1));
                v = fmaxf(v, __shfl_xor_sync(0xffffffffu, v, 2));
                if (tg == 0) Pmax[warpN*128 + warpM*32 + mt*16 + rr*8 + g] = v;
            }
        __syncthreads();
        if (tx < 128) {
            float m_old = Ms[tx];
            float m_new = fmaxf(m_old, fmaxf(Pmax[tx], Pmax[128 + tx]));
            float al = __expf(m_old - m_new);
            Al[tx] = al;
            Ls[tx] *= al;
            Ms[tx] = m_new;
        }
        __syncthreads();

        // exp, partial sums, write P [m][key] half
        float rsum[2][2];
#pragma unroll
        for (int mt = 0; mt < 2; mt++)
#pragma unroll
            for (int rr = 0; rr < 2; rr++) {
                int rowl = warpM*32 + mt*16 + rr*8 + g;
                float mrow = Ms[rowl];
                float sum = 0.f;
#pragma unroll
                for (int nt = 0; nt < 8; nt++) {
                    float p0 = __expf(s[mt][nt][rr*2 + 0] - mrow);
                    float p1 = __expf(s[mt][nt][rr*2 + 1] - mrow);
                    sum += p0 + p1;
                    int col = warpN*64 + nt*8 + tg*2;
                    *(half2*)&Ps[rowl*136 + col] = __floats2half2_rn(p0, p1);
                }
                rsum[mt][rr] = sum;
            }
#pragma unroll
        for (int mt = 0; mt < 2; mt++)
#pragma unroll
            for (int rr = 0; rr < 2; rr++) {
                float v = rsum[mt][rr];
                v += __shfl_xor_sync(0xffffffffu, v, 1);
                v += __shfl_xor_sync(0xffffffffu, v, 2);
                if (tg == 0) Psum[warpN*128 + warpM*32 + mt*16 + rr*8 + g] = v;
            }
        __syncthreads();
        if (tx < 128) Ls[tx] += Psum[tx] + Psum[128 + tx];

        // rescale O, then O += P @ V  (K = 128, 8 k16 steps)
        float alv[2][2];
#pragma unroll
        for (int mt = 0; mt < 2; mt++)
#pragma unroll
            for (int rr = 0; rr < 2; rr++)
                alv[mt][rr] = Al[warpM2*32 + mt*16 + rr*8 + g];
#pragma unroll
        for (int mt = 0; mt < 2; mt++)
#pragma unroll
            for (int nt = 0; nt < 4; nt++)
#pragma unroll
                for (int e = 0; e < 4; e++)
                    o[mt][nt][e] *= alv[mt][e >> 1];
#pragma unroll
        for (int ks = 0; ks < 8; ks++) {
            int kk = ks * 16;
            uint32_t a[2][4], b[4][2];
#pragma unroll
            for (int mt = 0; mt < 2; mt++)
                ldsm4(a[mt], pBase + (mt*16*136 + kk)*2);
#pragma unroll
            for (int np = 0; np < 2; np++) {
                uint32_t t4r[4];
                ldsm4(t4r, vBase + (np*16*136 + kk)*2);
                b[2*np  ][0] = t4r[0]; b[2*np  ][1] = t4r[1];
                b[2*np+1][0] = t4r[2]; b[2*np+1][1] = t4r[3];
            }
#pragma unroll
            for (int mt = 0; mt < 2; mt++)
#pragma unroll
                for (int nt = 0; nt < 4; nt++)
                    mma_f16(o[mt][nt], a[mt], b[nt]);
        }
    }
    __syncthreads();

    int b_ = bh / 12, head = bh % 12;
    float linv[2][2];
#pragma unroll
    for (int mt = 0; mt < 2; mt++)
#pragma unroll
        for (int rr = 0; rr < 2; rr++)
            linv[mt][rr] = 1.f / Ls[warpM2*32 + mt*16 + rr*8 + g];
#pragma unroll
    for (int mt = 0; mt < 2; mt++) {
#pragma unroll
        for (int nt = 0; nt < 4; nt++) {
#pragma unroll
            for (int e = 0; e < 4; e++) {
                int r = warpM2*32 + mt*16 + (e >> 1)*8 + g;
                int c = warpN2*32 + nt*8 + tg*2 + (e & 1);
                out[((size_t)(b_ * NSEQ + qt*128 + r)) * CH + head*64 + c] =
                    __float2half(o[mt][nt][e] * linv[mt][e >> 1]);
            }
        }
    }
}

// ---------------- orchestration ----------------
extern "C" void kernel_launch(void* const* d_in, const int* in_sizes, int n_in,
                              void* d_out, int out_size) {
    const float* x         = (const float*)d_in[0];
    const float* conv_w    = (const float*)d_in[1];
    const float* conv_b    = (const float*)d_in[2];
    const float* pos_embed = (const float*)d_in[3];
    const float* ln1_w     = (const float*)d_in[4];
    const float* ln1_b     = (const float*)d_in[5];
    const float* qkv_w     = (const float*)d_in[6];
    const float* qkv_b     = (const float*)d_in[7];
    const float* proj_w    = (const float*)d_in[8];
    const float* proj_b    = (const float*)d_in[9];
    const float* rel_pos_h = (const float*)d_in[10];
    const float* rel_pos_w = (const float*)d_in[11];
    const float* ln2_w     = (const float*)d_in[12];
    const float* ln2_b     = (const float*)d_in[13];
    const float* fc1_w     = (const float*)d_in[14];
    const float* fc1_b     = (const float*)d_in[15];
    const float* fc2_w     = (const float*)d_in[16];
    const float* fc2_b     = (const float*)d_in[17];

    float *h, *relh, *relw;
    __half *lnh, *colh, *wth, *qh, *kh, *vh, *aoh, *mlph;
    __half *wqkvh, *wprojh, *wfc1h, *wfc2h;
    cudaGetSymbolAddress((void**)&h,     g_h);
    cudaGetSymbolAddress((void**)&lnh,   g_lnh);
    cudaGetSymbolAddress((void**)&colh,  g_colh);
    cudaGetSymbolAddress((void**)&wth,   g_wth);
    cudaGetSymbolAddress((void**)&qh,    g_qh);
    cudaGetSymbolAddress((void**)&kh,    g_kh);
    cudaGetSymbolAddress((void**)&vh,    g_vh);
    cudaGetSymbolAddress((void**)&relh,  g_relh);
    cudaGetSymbolAddress((void**)&relw,  g_relw);
    cudaGetSymbolAddress((void**)&aoh,   g_aoh);
    cudaGetSymbolAddress((void**)&mlph,  g_mlph);
    cudaGetSymbolAddress((void**)&wqkvh, g_wqkvh);
    cudaGetSymbolAddress((void**)&wprojh,g_wprojh);
    cudaGetSymbolAddress((void**)&wfc1h, g_wfc1h);
    cudaGetSymbolAddress((void**)&wfc2h, g_wfc2h);

    static bool attr_set = false;
    if (!attr_set) {
        cudaFuncSetAttribute(flash_attn, cudaFuncAttributeMaxDynamicSharedMemorySize,
                             FA_SMEM_BYTES);
        attr_set = true;
    }

    dim3 tb(32, 8);
    wtrans_k<<<dim3(CH/32,  QKVD/32, 4), tb>>>(qkv_w,  wqkvh, CH,   QKVD);
    wtrans_k<<<dim3(CH/32,  CH/32,   4), tb>>>(proj_w, wprojh, CH,  CH);
    wtrans_k<<<dim3(CH/32,  MLPD/32, 4), tb>>>(fc1_w,  wfc1h, CH,   MLPD);
    wtrans_k<<<dim3(MLPD/32,CH/32,   4), tb>>>(fc2_w,  wfc2h, MLPD, CH);
    convhalf_k<<<CH*CH/256, 256>>>(conv_w, wth);

    im2col_k<<<TOK*CH/256, 256>>>(x, colh);
    gemm_h<4><<<dim3(CH/128, TOK/128), 256>>>(
        colh, wth, conv_b, pos_embed, h, nullptr, nullptr, nullptr, TOK, CH, CH);

    for (int i = 0; i < 4; i++) {
        layernorm_k<<<TOK, 256>>>(h, ln1_w + i*CH, ln1_b + i*CH, lnh);
        gemm_h<3><<<dim3(QKVD/128, TOK/128), 256>>>(
            lnh, wqkvh + (size_t)i*CH*QKVD, qkv_b + i*QKVD, nullptr,
            nullptr, qh, kh, vh, TOK, QKVD, CH);
        rel_k<<<BHD*NSEQ/8, 256>>>(qh, rel_pos_h + i*63*HD, rel_pos_w + i*63*HD,
                                   relh, relw);
        flash_attn<<<dim3(8, BHD), 256, FA_SMEM_BYTES>>>(qh, kh, vh, relh, relw, aoh);
        gemm_h<2><<<dim3(CH/128, TOK/128), 256>>>(
            aoh, wprojh + (size_t)i*CH*CH, proj_b + i*CH, h, h, nullptr,
            nullptr, nullptr, TOK, CH, CH);
        layernorm_k<<<TOK, 256>>>(h, ln2_w + i*CH, ln2_b + i*CH, lnh);
        gemm_h<1><<<dim3(MLPD/128, TOK/128), 256>>>(
            lnh, wfc1h + (size_t)i*CH*MLPD, fc1_b + i*MLPD, nullptr,
            nullptr, mlph, nullptr, nullptr, TOK, MLPD, CH);
        float* dst = (i == 3) ? (float*)d_out : h;
        gemm_h<2><<<dim3(CH/128, TOK/128), 256>>>(
            mlph, wfc2h + (size_t)i*MLPD*CH, fc2_b + i*CH, h, dst, nullptr,
            nullptr, nullptr, TOK, CH, MLPD);
    }
}